// round 14
// baseline (speedup 1.0000x reference)
#include <cuda_runtime.h>
#include <cuda_bf16.h>
#include <math.h>
#include <stdint.h>

#define MAXN 100000
#define MAXE 1600000
#define DHID 256
#define SCAN_ITEMS 2048   // 256 threads x 8 items

// ---------------- scratch (__device__ globals; allocation-free rule) ----------------
__device__ float          g_bufF[MAXN * DHID];       // fp32 GEMM output
__device__ __nv_bfloat16  g_bAHi[MAXN * DHID];       // bf16 split buffers (ping)
__device__ __nv_bfloat16  g_bALo[MAXN * DHID];
__device__ __nv_bfloat16  g_bBHi[MAXN * DHID];       // bf16 split buffers (pong)
__device__ __nv_bfloat16  g_bBLo[MAXN * DHID];
__device__ __nv_bfloat16  g_wtHi[3][65536];          // transposed weights, split
__device__ __nv_bfloat16  g_wtLo[3][65536];
__device__ float g_dinv[MAXN];
__device__ int   g_cnt   [MAXN];
__device__ int   g_rowptr[MAXN + 1];
__device__ int   g_cursor[MAXN];
__device__ int   g_blockSums[64];
__device__ int   g_edges[MAXE];                      // src node (4B/edge)

// final-output store: evict-first (nothing on the GPU re-reads d_out)
__device__ __forceinline__ void st_cs_f4(float* p, float4 v) {
    asm volatile("st.global.cs.v4.f32 [%0], {%1,%2,%3,%4};"
                 :: "l"(p), "f"(v.x), "f"(v.y), "f"(v.z), "f"(v.w) : "memory");
}

// ---------------- CSR build ----------------

__global__ void k_zero_cnt(int* cnt, int N) {
    int i = blockIdx.x * blockDim.x + threadIdx.x;
    if (i < N) cnt[i] = 0;
}

// 4 edges per thread via int4
__global__ void k_hist(const int* __restrict__ col, int* cnt, int E) {
    int i = (blockIdx.x * blockDim.x + threadIdx.x) * 4;
    if (i + 3 < E) {
        int4 c4 = *reinterpret_cast<const int4*>(&col[i]);
        atomicAdd(&cnt[c4.x], 1);
        atomicAdd(&cnt[c4.y], 1);
        atomicAdd(&cnt[c4.z], 1);
        atomicAdd(&cnt[c4.w], 1);
    } else {
        for (int j = i; j < E; j++) atomicAdd(&cnt[__ldg(&col[j])], 1);
    }
}

// scan1 + dinv fused
__global__ __launch_bounds__(256) void k_scan1d(const int* __restrict__ cnt,
                                                int* rowptr, int* blockSums,
                                                float* __restrict__ dinv, int N) {
    __shared__ int sh[256];
    int base = blockIdx.x * SCAN_ITEMS;
    int vals[8];
    int sum = 0;
    #pragma unroll
    for (int j = 0; j < 8; j++) {
        int idx = base + threadIdx.x * 8 + j;
        int v = (idx < N) ? cnt[idx] : 0;
        if (idx < N) dinv[idx] = rsqrtf((float)(v + 1));
        vals[j] = sum;
        sum += v;
    }
    sh[threadIdx.x] = sum;
    __syncthreads();
    #pragma unroll
    for (int off = 1; off < 256; off <<= 1) {
        int t = (threadIdx.x >= off) ? sh[threadIdx.x - off] : 0;
        __syncthreads();
        sh[threadIdx.x] += t;
        __syncthreads();
    }
    int thOff = (threadIdx.x > 0) ? sh[threadIdx.x - 1] : 0;
    #pragma unroll
    for (int j = 0; j < 8; j++) {
        int idx = base + threadIdx.x * 8 + j;
        if (idx < N) rowptr[idx] = thOff + vals[j];
    }
    if (threadIdx.x == 255) blockSums[blockIdx.x] = sh[255];
}

// scan2 + scan3 fused
__global__ __launch_bounds__(256) void k_scan3b(int* rowptr, int* cursor,
                                                const int* __restrict__ blockSums,
                                                int nb, int N, int E) {
    __shared__ int off[64];
    if (threadIdx.x < 64) off[threadIdx.x] = (threadIdx.x < nb) ? blockSums[threadIdx.x] : 0;
    __syncthreads();
    if (threadIdx.x == 0) {
        int s = 0;
        #pragma unroll
        for (int i = 0; i < 64; i++) { int t = off[i]; off[i] = s; s += t; }
    }
    __syncthreads();
    int i = blockIdx.x * blockDim.x + threadIdx.x;
    if (i < N) {
        int v = rowptr[i] + off[i / SCAN_ITEMS];
        rowptr[i] = v;
        cursor[i] = v;
    }
    if (i == 0) rowptr[N] = E;
}

// 4 edges per thread via int4
__global__ void k_scatter(const int* __restrict__ row, const int* __restrict__ col,
                          int* cursor, int* edges, int E) {
    int i = (blockIdx.x * blockDim.x + threadIdx.x) * 4;
    if (i + 3 < E) {
        int4 r4 = *reinterpret_cast<const int4*>(&row[i]);
        int4 c4 = *reinterpret_cast<const int4*>(&col[i]);
        int p0 = atomicAdd(&cursor[c4.x], 1); edges[p0] = r4.x;
        int p1 = atomicAdd(&cursor[c4.y], 1); edges[p1] = r4.y;
        int p2 = atomicAdd(&cursor[c4.z], 1); edges[p2] = r4.z;
        int p3 = atomicAdd(&cursor[c4.w], 1); edges[p3] = r4.w;
    } else {
        for (int j = i; j < E; j++) {
            int r = __ldg(&row[j]);
            int c = __ldg(&col[j]);
            int p = atomicAdd(&cursor[c], 1);
            edges[p] = r;
        }
    }
}

// ---------------- fp32 -> bf16 hi/lo split helpers ----------------

__device__ __forceinline__ void split2(float a, float b,
                                       __nv_bfloat162& hi, __nv_bfloat162& lo) {
    __nv_bfloat16 ha = __float2bfloat16(a);
    __nv_bfloat16 hb = __float2bfloat16(b);
    __nv_bfloat16 la = __float2bfloat16(a - __bfloat162float(ha));
    __nv_bfloat16 lb = __float2bfloat16(b - __bfloat162float(hb));
    hi = __halves2bfloat162(ha, hb);
    lo = __halves2bfloat162(la, lb);
}

// transpose + split all 3 weights in one launch.
__global__ void k_split_wt_all(const float* __restrict__ W0,
                               const float* __restrict__ W1,
                               const float* __restrict__ W2,
                               __nv_bfloat16* __restrict__ oh,
                               __nv_bfloat16* __restrict__ ol)
{
    int t = blockIdx.x * blockDim.x + threadIdx.x;
    if (t >= 131072) return;
    const float* W;
    int K, Nc, local, slot;
    if (t < 32768)       { W = W0; K = 128; Nc = 256; local = t;          slot = 0; }
    else if (t < 98304)  { W = W1; K = 256; Nc = 256; local = t - 32768;  slot = 1; }
    else                 { W = W2; K = 256; Nc = 128; local = t - 98304;  slot = 2; }
    int n = local / K, k = local % K;
    float a = W[k * Nc + n];
    __nv_bfloat16 h = __float2bfloat16(a);
    __nv_bfloat16 l = __float2bfloat16(a - __bfloat162float(h));
    oh[slot * 65536 + local] = h;
    ol[slot * 65536 + local] = l;
}

// ---------------- tensor-core GEMM via mma.sync (bf16, 3-term split) ----------------

#define GSTRIDE 40                       // smem row stride in bf16 (80 B)
#define TILE_BYTES (128 * GSTRIDE * 2)   // 10240 B per tile
#define BUF_BYTES  (4 * TILE_BYTES)
#define SMEM_TOTAL_G (2 * BUF_BYTES)     // 81920 B

__device__ __forceinline__ uint32_t smem_u32(const void* p) {
    uint32_t a;
    asm("{ .reg .u64 t; cvta.to.shared.u64 t, %1; cvt.u32.u64 %0, t; }" : "=r"(a) : "l"(p));
    return a;
}
__device__ __forceinline__ void cp16(uint32_t dst, const void* src, int srcsize) {
    asm volatile("cp.async.cg.shared.global [%0], [%1], 16, %2;"
                 :: "r"(dst), "l"(src), "r"(srcsize) : "memory");
}
__device__ __forceinline__ void cp_commit() {
    asm volatile("cp.async.commit_group;" ::: "memory");
}
template<int Ngroups>
__device__ __forceinline__ void cp_wait() {
    asm volatile("cp.async.wait_group %0;" :: "n"(Ngroups) : "memory");
}
__device__ __forceinline__ void mma16816(float* c, const uint32_t* a, const uint32_t* b) {
    asm volatile("mma.sync.aligned.m16n8k16.row.col.f32.bf16.bf16.f32 "
                 "{%0,%1,%2,%3}, {%4,%5,%6,%7}, {%8,%9}, {%0,%1,%2,%3};"
                 : "+f"(c[0]), "+f"(c[1]), "+f"(c[2]), "+f"(c[3])
                 : "r"(a[0]), "r"(a[1]), "r"(a[2]), "r"(a[3]), "r"(b[0]), "r"(b[1]));
}
__device__ __forceinline__ void ldsm_x4(uint32_t& r0, uint32_t& r1, uint32_t& r2,
                                        uint32_t& r3, uint32_t addr) {
    asm volatile("ldmatrix.sync.aligned.m8n8.x4.shared.b16 {%0,%1,%2,%3}, [%4];"
                 : "=r"(r0), "=r"(r1), "=r"(r2), "=r"(r3) : "r"(addr));
}

template<int EPI>
__global__ __launch_bounds__(256) void k_gemm_mma(
    const __nv_bfloat16* __restrict__ Ahi, const __nv_bfloat16* __restrict__ Alo,
    const __nv_bfloat16* __restrict__ Bhi, const __nv_bfloat16* __restrict__ Blo,
    float* __restrict__ C,
    const float* __restrict__ bias,
    __nv_bfloat16* __restrict__ outHi, __nv_bfloat16* __restrict__ outLo,
    int M, int K, int Nc, int n_base)
{
    extern __shared__ __align__(16) char smem[];
    const uint32_t sbase = smem_u32(smem);

    int tid = threadIdx.x;
    int wid = tid >> 5;
    int lane = tid & 31;
    int wm = wid & 3;
    int wn = wid >> 2;
    int g = lane >> 2;
    int q = lane & 3;
    int m0 = blockIdx.y * 128;
    int n0 = n_base + blockIdx.x * 128;

    // ldmatrix lane-address offsets (bytes within a tile)
    int lrA  = (lane & 7) + ((lane >> 3) & 1) * 8;
    int c16A = (lane >> 4) & 1;
    uint32_t aoffA[2];
    #pragma unroll
    for (int mi = 0; mi < 2; mi++)
        aoffA[mi] = (uint32_t)(wm * 32 + mi * 16 + lrA) * 80 + c16A * 16;
    uint32_t offB0 = (uint32_t)(wn * 64 + (lane & 7) + ((lane >> 4) & 1) * 8) * 80
                   + ((lane >> 3) & 1) * 16;

    float acc[2][8][4];
    #pragma unroll
    for (int mi = 0; mi < 2; mi++)
        #pragma unroll
        for (int ni = 0; ni < 8; ni++)
            #pragma unroll
            for (int r = 0; r < 4; r++) acc[mi][ni][r] = 0.f;

    int nchunks = K >> 5;

    auto load_chunk = [&](int c, int b) {
        uint32_t buf = sbase + b * BUF_BYTES;
        int kc = c * 32;
        #pragma unroll
        for (int i = 0; i < 2; i++) {
            int s   = tid + i * 256;
            int row = s >> 2;
            int cs  = s & 3;
            uint32_t soff = row * (GSTRIDE * 2) + cs * 16;
            int am = m0 + row;
            int ok = (am < M) ? 16 : 0;
            size_t aoff = (size_t)(ok ? am : 0) * K + kc + cs * 8;
            cp16(buf + 0 * TILE_BYTES + soff, Ahi + aoff, ok);
            cp16(buf + 1 * TILE_BYTES + soff, Alo + aoff, ok);
            size_t boff = (size_t)(n0 + row) * K + kc + cs * 8;
            cp16(buf + 2 * TILE_BYTES + soff, Bhi + boff, 16);
            cp16(buf + 3 * TILE_BYTES + soff, Blo + boff, 16);
        }
        cp_commit();
    };

    load_chunk(0, 0);

    for (int c = 0; c < nchunks; c++) {
        if (c + 1 < nchunks) {
            load_chunk(c + 1, (c + 1) & 1);
            cp_wait<1>();
        } else {
            cp_wait<0>();
        }
        __syncthreads();

        uint32_t buf = sbase + (c & 1) * BUF_BYTES;
        uint32_t aHi = buf + 0 * TILE_BYTES;
        uint32_t aLo = buf + 1 * TILE_BYTES;
        uint32_t bHi = buf + 2 * TILE_BYTES;
        uint32_t bLo = buf + 3 * TILE_BYTES;

        #pragma unroll
        for (int ks = 0; ks < 2; ks++) {
            int kb = ks * 32;
            uint32_t ah[2][4], al[2][4];
            #pragma unroll
            for (int mi = 0; mi < 2; mi++) {
                ldsm_x4(ah[mi][0], ah[mi][1], ah[mi][2], ah[mi][3], aHi + aoffA[mi] + kb);
                ldsm_x4(al[mi][0], al[mi][1], al[mi][2], al[mi][3], aLo + aoffA[mi] + kb);
            }
            #pragma unroll
            for (int p = 0; p < 4; p++) {
                uint32_t bh[4], bl[4];
                ldsm_x4(bh[0], bh[1], bh[2], bh[3], bHi + offB0 + p * 1280 + kb);
                ldsm_x4(bl[0], bl[1], bl[2], bl[3], bLo + offB0 + p * 1280 + kb);
                #pragma unroll
                for (int mi = 0; mi < 2; mi++) {
                    mma16816(acc[mi][2 * p],     ah[mi], &bh[0]);
                    mma16816(acc[mi][2 * p],     ah[mi], &bl[0]);
                    mma16816(acc[mi][2 * p],     al[mi], &bh[0]);
                    mma16816(acc[mi][2 * p + 1], ah[mi], &bh[2]);
                    mma16816(acc[mi][2 * p + 1], ah[mi], &bl[2]);
                    mma16816(acc[mi][2 * p + 1], al[mi], &bh[2]);
                }
            }
        }
        __syncthreads();
    }

    // ---- epilogue (normal stores: consumers re-read these from L2) ----
    #pragma unroll
    for (int mi = 0; mi < 2; mi++) {
        int r0 = m0 + wm * 32 + mi * 16 + g;
        int r1 = r0 + 8;
        #pragma unroll
        for (int ni = 0; ni < 8; ni++) {
            int colg = n0 + wn * 64 + ni * 8 + q * 2;
            if (EPI == 0) {
                if (r0 < M)
                    *reinterpret_cast<float2*>(&C[(size_t)r0 * Nc + colg]) =
                        make_float2(acc[mi][ni][0], acc[mi][ni][1]);
                if (r1 < M)
                    *reinterpret_cast<float2*>(&C[(size_t)r1 * Nc + colg]) =
                        make_float2(acc[mi][ni][2], acc[mi][ni][3]);
            } else {
                float2 bb = *reinterpret_cast<const float2*>(&bias[colg]);
                if (r0 < M) {
                    float v0 = fmaxf(acc[mi][ni][0] + bb.x, 0.f);
                    float v1 = fmaxf(acc[mi][ni][1] + bb.y, 0.f);
                    __nv_bfloat162 h, l;
                    split2(v0, v1, h, l);
                    *reinterpret_cast<__nv_bfloat162*>(&outHi[(size_t)r0 * Nc + colg]) = h;
                    *reinterpret_cast<__nv_bfloat162*>(&outLo[(size_t)r0 * Nc + colg]) = l;
                }
                if (r1 < M) {
                    float v0 = fmaxf(acc[mi][ni][2] + bb.x, 0.f);
                    float v1 = fmaxf(acc[mi][ni][3] + bb.y, 0.f);
                    __nv_bfloat162 h, l;
                    split2(v0, v1, h, l);
                    *reinterpret_cast<__nv_bfloat162*>(&outHi[(size_t)r1 * Nc + colg]) = h;
                    *reinterpret_cast<__nv_bfloat162*>(&outLo[(size_t)r1 * Nc + colg]) = l;
                }
            }
        }
    }
}

// ---------------- aggregation: CSR gather, one warp per destination ----------------
// Processes a 128-column slice [off, off+128) of a [N, DTOT] matrix per launch.
// out = [bias +] dinv[n]^2*hw[n,:] + sum_e dinv[src]*dinv[n]*hw[src,:]
// FINAL: evict-first store to d_out.

template<int DTOT, bool RELU, bool SPLIT, bool FINAL>
__global__ __launch_bounds__(256) void k_gather(const float* __restrict__ hw,
                                                const float* __restrict__ bias,
                                                const float* __restrict__ dinv,
                                                const int* __restrict__ rowptr,
                                                const int* __restrict__ edges,
                                                float* __restrict__ out,
                                                __nv_bfloat16* __restrict__ outHi,
                                                __nv_bfloat16* __restrict__ outLo,
                                                int N, int off)
{
    int n    = (blockIdx.x * blockDim.x + threadIdx.x) >> 5;
    int lane = threadIdx.x & 31;
    if (n >= N) return;

    float di = dinv[n];
    float w  = di * di;
    int f = off + lane * 4;

    float4 acc;
    {
        float4 v  = *reinterpret_cast<const float4*>(&hw[(size_t)n * DTOT + f]);
        float4 bb = bias ? *reinterpret_cast<const float4*>(&bias[f])
                         : make_float4(0.f, 0.f, 0.f, 0.f);
        acc.x = fmaf(v.x, w, bb.x);
        acc.y = fmaf(v.y, w, bb.y);
        acc.z = fmaf(v.z, w, bb.z);
        acc.w = fmaf(v.w, w, bb.w);
    }

    int e   = rowptr[n];
    int end = rowptr[n + 1];

    for (; e + 3 < end; e += 4) {
        int s0i = __ldg(&edges[e]);
        int s1i = __ldg(&edges[e + 1]);
        int s2i = __ldg(&edges[e + 2]);
        int s3i = __ldg(&edges[e + 3]);
        float c0 = __ldg(&dinv[s0i]) * di;
        float c1 = __ldg(&dinv[s1i]) * di;
        float c2 = __ldg(&dinv[s2i]) * di;
        float c3 = __ldg(&dinv[s3i]) * di;
        float4 v0 = *reinterpret_cast<const float4*>(&hw[(size_t)s0i * DTOT + f]);
        float4 v1 = *reinterpret_cast<const float4*>(&hw[(size_t)s1i * DTOT + f]);
        float4 v2 = *reinterpret_cast<const float4*>(&hw[(size_t)s2i * DTOT + f]);
        float4 v3 = *reinterpret_cast<const float4*>(&hw[(size_t)s3i * DTOT + f]);
        acc.x = fmaf(v0.x, c0, acc.x); acc.y = fmaf(v0.y, c0, acc.y);
        acc.z = fmaf(v0.z, c0, acc.z); acc.w = fmaf(v0.w, c0, acc.w);
        acc.x = fmaf(v1.x, c1, acc.x); acc.y = fmaf(v1.y, c1, acc.y);
        acc.z = fmaf(v1.z, c1, acc.z); acc.w = fmaf(v1.w, c1, acc.w);
        acc.x = fmaf(v2.x, c2, acc.x); acc.y = fmaf(v2.y, c2, acc.y);
        acc.z = fmaf(v2.z, c2, acc.z); acc.w = fmaf(v2.w, c2, acc.w);
        acc.x = fmaf(v3.x, c3, acc.x); acc.y = fmaf(v3.y, c3, acc.y);
        acc.z = fmaf(v3.z, c3, acc.z); acc.w = fmaf(v3.w, c3, acc.w);
    }
    for (; e < end; e++) {
        int s0i = __ldg(&edges[e]);
        float c0 = __ldg(&dinv[s0i]) * di;
        float4 v0 = *reinterpret_cast<const float4*>(&hw[(size_t)s0i * DTOT + f]);
        acc.x = fmaf(v0.x, c0, acc.x); acc.y = fmaf(v0.y, c0, acc.y);
        acc.z = fmaf(v0.z, c0, acc.z); acc.w = fmaf(v0.w, c0, acc.w);
    }

    if (RELU) {
        acc.x = fmaxf(acc.x, 0.f); acc.y = fmaxf(acc.y, 0.f);
        acc.z = fmaxf(acc.z, 0.f); acc.w = fmaxf(acc.w, 0.f);
    }
    if (SPLIT) {
        __nv_bfloat162 h0, l0, h1, l1;
        split2(acc.x, acc.y, h0, l0);
        split2(acc.z, acc.w, h1, l1);
        *reinterpret_cast<__nv_bfloat162*>(&outHi[(size_t)n * DTOT + f])     = h0;
        *reinterpret_cast<__nv_bfloat162*>(&outHi[(size_t)n * DTOT + f + 2]) = h1;
        *reinterpret_cast<__nv_bfloat162*>(&outLo[(size_t)n * DTOT + f])     = l0;
        *reinterpret_cast<__nv_bfloat162*>(&outLo[(size_t)n * DTOT + f + 2]) = l1;
    } else if (FINAL) {
        st_cs_f4(&out[(size_t)n * DTOT + f], acc);
    } else {
        *reinterpret_cast<float4*>(&out[(size_t)n * DTOT + f]) = acc;
    }
}

// ---------------- launch ----------------

extern "C" void kernel_launch(void* const* d_in, const int* in_sizes, int n_in,
                              void* d_out, int out_size)
{
    const float* x  = (const float*)d_in[0];
    const int*   ei = (const int*)  d_in[1];
    const float* W0 = (const float*)d_in[4];
    const float* b0 = (const float*)d_in[5];
    const float* W1 = (const float*)d_in[6];
    const float* b1 = (const float*)d_in[7];
    const float* W2 = (const float*)d_in[8];
    const float* b2 = (const float*)d_in[9];

    int N = in_sizes[0] / 128;
    int E = in_sizes[1] / 2;
    const int* rowp = ei;
    const int* colp = ei + E;

    float *bufF, *dinv;
    __nv_bfloat16 *bAHi, *bALo, *bBHi, *bBLo, *wtHi, *wtLo;
    int *cnt, *rowptr, *cursor, *blockSums;
    int *edges;
    cudaGetSymbolAddress((void**)&bufF,      g_bufF);
    cudaGetSymbolAddress((void**)&bAHi,      g_bAHi);
    cudaGetSymbolAddress((void**)&bALo,      g_bALo);
    cudaGetSymbolAddress((void**)&bBHi,      g_bBHi);
    cudaGetSymbolAddress((void**)&bBLo,      g_bBLo);
    cudaGetSymbolAddress((void**)&wtHi,      g_wtHi);
    cudaGetSymbolAddress((void**)&wtLo,      g_wtLo);
    cudaGetSymbolAddress((void**)&dinv,      g_dinv);
    cudaGetSymbolAddress((void**)&cnt,       g_cnt);
    cudaGetSymbolAddress((void**)&rowptr,    g_rowptr);
    cudaGetSymbolAddress((void**)&cursor,    g_cursor);
    cudaGetSymbolAddress((void**)&blockSums, g_blockSums);
    cudaGetSymbolAddress((void**)&edges,     g_edges);

    float* outp = (float*)d_out;

    static cudaStream_t s2 = nullptr;
    static cudaEvent_t evFork = nullptr, evJoin = nullptr, evT0 = nullptr, evP1 = nullptr;
    static bool initDone = false;
    if (!initDone) {
        cudaFuncSetAttribute(k_gemm_mma<0>, cudaFuncAttributeMaxDynamicSharedMemorySize,
                             SMEM_TOTAL_G);
        cudaFuncSetAttribute(k_gemm_mma<1>, cudaFuncAttributeMaxDynamicSharedMemorySize,
                             SMEM_TOTAL_G);
        cudaStreamCreateWithFlags(&s2, cudaStreamNonBlocking);
        cudaEventCreateWithFlags(&evFork, cudaEventDisableTiming);
        cudaEventCreateWithFlags(&evJoin, cudaEventDisableTiming);
        cudaEventCreateWithFlags(&evT0,   cudaEventDisableTiming);
        cudaEventCreateWithFlags(&evP1,   cudaEventDisableTiming);
        initDone = true;
    }

    int nb = (N + SCAN_ITEMS - 1) / SCAN_ITEMS;

    // ---- fork: fused weight split on side stream
    cudaEventRecord(evFork, 0);
    cudaStreamWaitEvent(s2, evFork, 0);
    k_split_wt_all<<<(131072 + 255) / 256, 256, 0, s2>>>(W0, W1, W2, wtHi, wtLo);
    cudaEventRecord(evJoin, s2);

    // ---- main stream: CSR build + norm
    k_zero_cnt<<<(N + 255) / 256, 256>>>(cnt, N);
    k_hist    <<<(E / 4 + 255) / 256, 256>>>(colp, cnt, E);
    k_scan1d  <<<nb, 256>>>(cnt, rowptr, blockSums, dinv, N);
    k_scan3b  <<<(N + 255) / 256, 256>>>(rowptr, cursor, blockSums, nb, N, E);
    k_scatter <<<(E / 4 + 255) / 256, 256>>>(rowp, colp, cursor, edges, E);

    int mt = (N + 127) / 128;
    int gatherBlocks = (N * 32 + 255) / 256;

    // L0 (aggregate-first): xa = Â x (D=128), split -> bA
    k_gather<128, false, true, false><<<gatherBlocks, 256>>>(x, nullptr, dinv, rowptr, edges,
                                                             nullptr, bAHi, bALo, N, 0);

    cudaStreamWaitEvent(0, evJoin, 0);

    // GEMM0: h1 = relu(xa@W0 + b0), split epilogue -> bB
    k_gemm_mma<1><<<dim3(2, mt), 256, SMEM_TOTAL_G>>>(bAHi, bALo,
                                                      wtHi + 0 * 65536, wtLo + 0 * 65536,
                                                      nullptr, b0, bBHi, bBLo, N, 128, 256, 0);

    // L1 GEMM as two n-tiles; gather pass1 (cols 0-127) overlaps tile1 on s2
    k_gemm_mma<0><<<dim3(1, mt), 256, SMEM_TOTAL_G>>>(bBHi, bBLo,
                                                      wtHi + 1 * 65536, wtLo + 1 * 65536,
                                                      bufF, nullptr, nullptr, nullptr,
                                                      N, 256, 256, 0);
    cudaEventRecord(evT0, 0);
    k_gemm_mma<0><<<dim3(1, mt), 256, SMEM_TOTAL_G>>>(bBHi, bBLo,
                                                      wtHi + 1 * 65536, wtLo + 1 * 65536,
                                                      bufF, nullptr, nullptr, nullptr,
                                                      N, 256, 256, 128);
    // s2: gather pass1 as soon as tile0 is done (concurrent with tile1)
    cudaStreamWaitEvent(s2, evT0, 0);
    k_gather<256, true, true, false><<<gatherBlocks, 256, 0, s2>>>(bufF, b1, dinv, rowptr, edges,
                                                                   nullptr, bAHi, bALo, N, 0);
    cudaEventRecord(evP1, s2);
    // main: gather pass2 after tile1
    k_gather<256, true, true, false><<<gatherBlocks, 256>>>(bufF, b1, dinv, rowptr, edges,
                                                            nullptr, bAHi, bALo, N, 128);
    cudaStreamWaitEvent(0, evP1, 0);

    // L2: bufF = h2@W2 (D=128); out = Â bufF + b2
    k_gemm_mma<0><<<dim3(1, mt), 256, SMEM_TOTAL_G>>>(bAHi, bALo,
                                                      wtHi + 2 * 65536, wtLo + 2 * 65536,
                                                      bufF, nullptr, nullptr, nullptr,
                                                      N, 256, 128, 0);
    k_gather<128, false, false, true><<<gatherBlocks, 256>>>(bufF, b2, dinv, rowptr, edges,
                                                             outp, nullptr, nullptr, N, 0);
}

// round 15
// speedup vs baseline: 1.0133x; 1.0133x over previous
#include <cuda_runtime.h>
#include <cuda_bf16.h>
#include <math.h>
#include <stdint.h>

#define MAXN 100000
#define MAXE 1600000
#define DHID 256
#define SCAN_ITEMS 2048   // 256 threads x 8 items

// ---------------- scratch (__device__ globals; allocation-free rule) ----------------
__device__ float          g_bufF[MAXN * DHID];       // fp32 GEMM output
__device__ __nv_bfloat16  g_bAHi[MAXN * DHID];       // bf16 split buffers (ping)
__device__ __nv_bfloat16  g_bALo[MAXN * DHID];
__device__ __nv_bfloat16  g_bBHi[MAXN * DHID];       // bf16 split buffers (pong)
__device__ __nv_bfloat16  g_bBLo[MAXN * DHID];
__device__ __nv_bfloat16  g_wtHi[3][65536];          // transposed weights, split
__device__ __nv_bfloat16  g_wtLo[3][65536];
__device__ float g_dinv[MAXN];
__device__ int   g_cnt   [MAXN];
__device__ int   g_rowptr[MAXN + 1];
__device__ int   g_cursor[MAXN];
__device__ int   g_blockSums[64];
__device__ int   g_edges[MAXE];                      // src node (4B/edge)

// final-output store: evict-first (nothing on the GPU re-reads d_out)
__device__ __forceinline__ void st_cs_f4(float* p, float4 v) {
    asm volatile("st.global.cs.v4.f32 [%0], {%1,%2,%3,%4};"
                 :: "l"(p), "f"(v.x), "f"(v.y), "f"(v.z), "f"(v.w) : "memory");
}

// ---------------- CSR build ----------------

// 4 edges per thread via int4
__global__ void k_hist(const int* __restrict__ col, int* cnt, int E) {
    int i = (blockIdx.x * blockDim.x + threadIdx.x) * 4;
    if (i + 3 < E) {
        int4 c4 = *reinterpret_cast<const int4*>(&col[i]);
        atomicAdd(&cnt[c4.x], 1);
        atomicAdd(&cnt[c4.y], 1);
        atomicAdd(&cnt[c4.z], 1);
        atomicAdd(&cnt[c4.w], 1);
    } else {
        for (int j = i; j < E; j++) atomicAdd(&cnt[__ldg(&col[j])], 1);
    }
}

// scan1 + dinv fused
__global__ __launch_bounds__(256) void k_scan1d(const int* __restrict__ cnt,
                                                int* rowptr, int* blockSums,
                                                float* __restrict__ dinv, int N) {
    __shared__ int sh[256];
    int base = blockIdx.x * SCAN_ITEMS;
    int vals[8];
    int sum = 0;
    #pragma unroll
    for (int j = 0; j < 8; j++) {
        int idx = base + threadIdx.x * 8 + j;
        int v = (idx < N) ? cnt[idx] : 0;
        if (idx < N) dinv[idx] = rsqrtf((float)(v + 1));
        vals[j] = sum;
        sum += v;
    }
    sh[threadIdx.x] = sum;
    __syncthreads();
    #pragma unroll
    for (int off = 1; off < 256; off <<= 1) {
        int t = (threadIdx.x >= off) ? sh[threadIdx.x - off] : 0;
        __syncthreads();
        sh[threadIdx.x] += t;
        __syncthreads();
    }
    int thOff = (threadIdx.x > 0) ? sh[threadIdx.x - 1] : 0;
    #pragma unroll
    for (int j = 0; j < 8; j++) {
        int idx = base + threadIdx.x * 8 + j;
        if (idx < N) rowptr[idx] = thOff + vals[j];
    }
    if (threadIdx.x == 255) blockSums[blockIdx.x] = sh[255];
}

// scan2 + scan3 fused
__global__ __launch_bounds__(256) void k_scan3b(int* rowptr, int* cursor,
                                                const int* __restrict__ blockSums,
                                                int nb, int N, int E) {
    __shared__ int off[64];
    if (threadIdx.x < 64) off[threadIdx.x] = (threadIdx.x < nb) ? blockSums[threadIdx.x] : 0;
    __syncthreads();
    if (threadIdx.x == 0) {
        int s = 0;
        #pragma unroll
        for (int i = 0; i < 64; i++) { int t = off[i]; off[i] = s; s += t; }
    }
    __syncthreads();
    int i = blockIdx.x * blockDim.x + threadIdx.x;
    if (i < N) {
        int v = rowptr[i] + off[i / SCAN_ITEMS];
        rowptr[i] = v;
        cursor[i] = v;
    }
    if (i == 0) rowptr[N] = E;
}

// 4 edges per thread via int4
__global__ void k_scatter(const int* __restrict__ row, const int* __restrict__ col,
                          int* cursor, int* edges, int E) {
    int i = (blockIdx.x * blockDim.x + threadIdx.x) * 4;
    if (i + 3 < E) {
        int4 r4 = *reinterpret_cast<const int4*>(&row[i]);
        int4 c4 = *reinterpret_cast<const int4*>(&col[i]);
        int p0 = atomicAdd(&cursor[c4.x], 1); edges[p0] = r4.x;
        int p1 = atomicAdd(&cursor[c4.y], 1); edges[p1] = r4.y;
        int p2 = atomicAdd(&cursor[c4.z], 1); edges[p2] = r4.z;
        int p3 = atomicAdd(&cursor[c4.w], 1); edges[p3] = r4.w;
    } else {
        for (int j = i; j < E; j++) {
            int r = __ldg(&row[j]);
            int c = __ldg(&col[j]);
            int p = atomicAdd(&cursor[c], 1);
            edges[p] = r;
        }
    }
}

// ---------------- fp32 -> bf16 hi/lo split helpers ----------------

__device__ __forceinline__ void split2(float a, float b,
                                       __nv_bfloat162& hi, __nv_bfloat162& lo) {
    __nv_bfloat16 ha = __float2bfloat16(a);
    __nv_bfloat16 hb = __float2bfloat16(b);
    __nv_bfloat16 la = __float2bfloat16(a - __bfloat162float(ha));
    __nv_bfloat16 lb = __float2bfloat16(b - __bfloat162float(hb));
    hi = __halves2bfloat162(ha, hb);
    lo = __halves2bfloat162(la, lb);
}

// transpose + split all 3 weights in one launch.
__global__ void k_split_wt_all(const float* __restrict__ W0,
                               const float* __restrict__ W1,
                               const float* __restrict__ W2,
                               __nv_bfloat16* __restrict__ oh,
                               __nv_bfloat16* __restrict__ ol)
{
    int t = blockIdx.x * blockDim.x + threadIdx.x;
    if (t >= 131072) return;
    const float* W;
    int K, Nc, local, slot;
    if (t < 32768)       { W = W0; K = 128; Nc = 256; local = t;          slot = 0; }
    else if (t < 98304)  { W = W1; K = 256; Nc = 256; local = t - 32768;  slot = 1; }
    else                 { W = W2; K = 256; Nc = 128; local = t - 98304;  slot = 2; }
    int n = local / K, k = local % K;
    float a = W[k * Nc + n];
    __nv_bfloat16 h = __float2bfloat16(a);
    __nv_bfloat16 l = __float2bfloat16(a - __bfloat162float(h));
    oh[slot * 65536 + local] = h;
    ol[slot * 65536 + local] = l;
}

// ---------------- tensor-core GEMM via mma.sync (bf16, 3-term split) ----------------

#define GSTRIDE 40                       // smem row stride in bf16 (80 B)
#define TILE_BYTES (128 * GSTRIDE * 2)   // 10240 B per tile
#define BUF_BYTES  (4 * TILE_BYTES)
#define SMEM_TOTAL_G (2 * BUF_BYTES)     // 81920 B

__device__ __forceinline__ uint32_t smem_u32(const void* p) {
    uint32_t a;
    asm("{ .reg .u64 t; cvta.to.shared.u64 t, %1; cvt.u32.u64 %0, t; }" : "=r"(a) : "l"(p));
    return a;
}
__device__ __forceinline__ void cp16(uint32_t dst, const void* src, int srcsize) {
    asm volatile("cp.async.cg.shared.global [%0], [%1], 16, %2;"
                 :: "r"(dst), "l"(src), "r"(srcsize) : "memory");
}
__device__ __forceinline__ void cp_commit() {
    asm volatile("cp.async.commit_group;" ::: "memory");
}
template<int Ngroups>
__device__ __forceinline__ void cp_wait() {
    asm volatile("cp.async.wait_group %0;" :: "n"(Ngroups) : "memory");
}
__device__ __forceinline__ void mma16816(float* c, const uint32_t* a, const uint32_t* b) {
    asm volatile("mma.sync.aligned.m16n8k16.row.col.f32.bf16.bf16.f32 "
                 "{%0,%1,%2,%3}, {%4,%5,%6,%7}, {%8,%9}, {%0,%1,%2,%3};"
                 : "+f"(c[0]), "+f"(c[1]), "+f"(c[2]), "+f"(c[3])
                 : "r"(a[0]), "r"(a[1]), "r"(a[2]), "r"(a[3]), "r"(b[0]), "r"(b[1]));
}
__device__ __forceinline__ void ldsm_x4(uint32_t& r0, uint32_t& r1, uint32_t& r2,
                                        uint32_t& r3, uint32_t addr) {
    asm volatile("ldmatrix.sync.aligned.m8n8.x4.shared.b16 {%0,%1,%2,%3}, [%4];"
                 : "=r"(r0), "=r"(r1), "=r"(r2), "=r"(r3) : "r"(addr));
}

template<int EPI>
__global__ __launch_bounds__(256) void k_gemm_mma(
    const __nv_bfloat16* __restrict__ Ahi, const __nv_bfloat16* __restrict__ Alo,
    const __nv_bfloat16* __restrict__ Bhi, const __nv_bfloat16* __restrict__ Blo,
    float* __restrict__ C,
    const float* __restrict__ bias,
    __nv_bfloat16* __restrict__ outHi, __nv_bfloat16* __restrict__ outLo,
    int M, int K, int Nc)
{
    extern __shared__ __align__(16) char smem[];
    const uint32_t sbase = smem_u32(smem);

    int tid = threadIdx.x;
    int wid = tid >> 5;
    int lane = tid & 31;
    int wm = wid & 3;
    int wn = wid >> 2;
    int g = lane >> 2;
    int q = lane & 3;
    int m0 = blockIdx.y * 128;
    int n0 = blockIdx.x * 128;

    // ldmatrix lane-address offsets (bytes within a tile)
    int lrA  = (lane & 7) + ((lane >> 3) & 1) * 8;
    int c16A = (lane >> 4) & 1;
    uint32_t aoffA[2];
    #pragma unroll
    for (int mi = 0; mi < 2; mi++)
        aoffA[mi] = (uint32_t)(wm * 32 + mi * 16 + lrA) * 80 + c16A * 16;
    uint32_t offB0 = (uint32_t)(wn * 64 + (lane & 7) + ((lane >> 4) & 1) * 8) * 80
                   + ((lane >> 3) & 1) * 16;

    float acc[2][8][4];
    #pragma unroll
    for (int mi = 0; mi < 2; mi++)
        #pragma unroll
        for (int ni = 0; ni < 8; ni++)
            #pragma unroll
            for (int r = 0; r < 4; r++) acc[mi][ni][r] = 0.f;

    int nchunks = K >> 5;

    auto load_chunk = [&](int c, int b) {
        uint32_t buf = sbase + b * BUF_BYTES;
        int kc = c * 32;
        #pragma unroll
        for (int i = 0; i < 2; i++) {
            int s   = tid + i * 256;
            int row = s >> 2;
            int cs  = s & 3;
            uint32_t soff = row * (GSTRIDE * 2) + cs * 16;
            int am = m0 + row;
            int ok = (am < M) ? 16 : 0;
            size_t aoff = (size_t)(ok ? am : 0) * K + kc + cs * 8;
            cp16(buf + 0 * TILE_BYTES + soff, Ahi + aoff, ok);
            cp16(buf + 1 * TILE_BYTES + soff, Alo + aoff, ok);
            size_t boff = (size_t)(n0 + row) * K + kc + cs * 8;
            cp16(buf + 2 * TILE_BYTES + soff, Bhi + boff, 16);
            cp16(buf + 3 * TILE_BYTES + soff, Blo + boff, 16);
        }
        cp_commit();
    };

    load_chunk(0, 0);

    for (int c = 0; c < nchunks; c++) {
        if (c + 1 < nchunks) {
            load_chunk(c + 1, (c + 1) & 1);
            cp_wait<1>();
        } else {
            cp_wait<0>();
        }
        __syncthreads();

        uint32_t buf = sbase + (c & 1) * BUF_BYTES;
        uint32_t aHi = buf + 0 * TILE_BYTES;
        uint32_t aLo = buf + 1 * TILE_BYTES;
        uint32_t bHi = buf + 2 * TILE_BYTES;
        uint32_t bLo = buf + 3 * TILE_BYTES;

        #pragma unroll
        for (int ks = 0; ks < 2; ks++) {
            int kb = ks * 32;
            uint32_t ah[2][4], al[2][4];
            #pragma unroll
            for (int mi = 0; mi < 2; mi++) {
                ldsm_x4(ah[mi][0], ah[mi][1], ah[mi][2], ah[mi][3], aHi + aoffA[mi] + kb);
                ldsm_x4(al[mi][0], al[mi][1], al[mi][2], al[mi][3], aLo + aoffA[mi] + kb);
            }
            #pragma unroll
            for (int p = 0; p < 4; p++) {
                uint32_t bh[4], bl[4];
                ldsm_x4(bh[0], bh[1], bh[2], bh[3], bHi + offB0 + p * 1280 + kb);
                ldsm_x4(bl[0], bl[1], bl[2], bl[3], bLo + offB0 + p * 1280 + kb);
                #pragma unroll
                for (int mi = 0; mi < 2; mi++) {
                    mma16816(acc[mi][2 * p],     ah[mi], &bh[0]);
                    mma16816(acc[mi][2 * p],     ah[mi], &bl[0]);
                    mma16816(acc[mi][2 * p],     al[mi], &bh[0]);
                    mma16816(acc[mi][2 * p + 1], ah[mi], &bh[2]);
                    mma16816(acc[mi][2 * p + 1], ah[mi], &bl[2]);
                    mma16816(acc[mi][2 * p + 1], al[mi], &bh[2]);
                }
            }
        }
        __syncthreads();
    }

    // ---- epilogue (normal stores: consumers re-read these from L2) ----
    #pragma unroll
    for (int mi = 0; mi < 2; mi++) {
        int r0 = m0 + wm * 32 + mi * 16 + g;
        int r1 = r0 + 8;
        #pragma unroll
        for (int ni = 0; ni < 8; ni++) {
            int colg = n0 + wn * 64 + ni * 8 + q * 2;
            if (EPI == 0) {
                if (r0 < M)
                    *reinterpret_cast<float2*>(&C[(size_t)r0 * Nc + colg]) =
                        make_float2(acc[mi][ni][0], acc[mi][ni][1]);
                if (r1 < M)
                    *reinterpret_cast<float2*>(&C[(size_t)r1 * Nc + colg]) =
                        make_float2(acc[mi][ni][2], acc[mi][ni][3]);
            } else {
                float2 bb = *reinterpret_cast<const float2*>(&bias[colg]);
                if (r0 < M) {
                    float v0 = fmaxf(acc[mi][ni][0] + bb.x, 0.f);
                    float v1 = fmaxf(acc[mi][ni][1] + bb.y, 0.f);
                    __nv_bfloat162 h, l;
                    split2(v0, v1, h, l);
                    *reinterpret_cast<__nv_bfloat162*>(&outHi[(size_t)r0 * Nc + colg]) = h;
                    *reinterpret_cast<__nv_bfloat162*>(&outLo[(size_t)r0 * Nc + colg]) = l;
                }
                if (r1 < M) {
                    float v0 = fmaxf(acc[mi][ni][2] + bb.x, 0.f);
                    float v1 = fmaxf(acc[mi][ni][3] + bb.y, 0.f);
                    __nv_bfloat162 h, l;
                    split2(v0, v1, h, l);
                    *reinterpret_cast<__nv_bfloat162*>(&outHi[(size_t)r1 * Nc + colg]) = h;
                    *reinterpret_cast<__nv_bfloat162*>(&outLo[(size_t)r1 * Nc + colg]) = l;
                }
            }
        }
    }
}

// ---------------- aggregation: CSR gather, one warp per destination ----------------
// Processes the 128-column slice [off0 + blockIdx.y*128, +128) of a [N, DTOT] matrix.
// blockIdx.y indexes feature passes (x-major CTA order drains pass 0 first,
// preserving the L2-residency phasing while saving a launch).
// out = [bias +] dinv[n]^2*hw[n,:] + sum_e dinv[src]*dinv[n]*hw[src,:]
// FINAL: evict-first store to d_out.

template<int DTOT, bool RELU, bool SPLIT, bool FINAL>
__global__ __launch_bounds__(256) void k_gather(const float* __restrict__ hw,
                                                const float* __restrict__ bias,
                                                const float* __restrict__ dinv,
                                                const int* __restrict__ rowptr,
                                                const int* __restrict__ edges,
                                                float* __restrict__ out,
                                                __nv_bfloat16* __restrict__ outHi,
                                                __nv_bfloat16* __restrict__ outLo,
                                                int N, int off0)
{
    int n    = (blockIdx.x * blockDim.x + threadIdx.x) >> 5;
    int lane = threadIdx.x & 31;
    if (n >= N) return;

    float di = dinv[n];
    float w  = di * di;
    int f = off0 + blockIdx.y * 128 + lane * 4;

    float4 acc;
    {
        float4 v  = *reinterpret_cast<const float4*>(&hw[(size_t)n * DTOT + f]);
        float4 bb = bias ? *reinterpret_cast<const float4*>(&bias[f])
                         : make_float4(0.f, 0.f, 0.f, 0.f);
        acc.x = fmaf(v.x, w, bb.x);
        acc.y = fmaf(v.y, w, bb.y);
        acc.z = fmaf(v.z, w, bb.z);
        acc.w = fmaf(v.w, w, bb.w);
    }

    int e   = rowptr[n];
    int end = rowptr[n + 1];

    for (; e + 3 < end; e += 4) {
        int s0i = __ldg(&edges[e]);
        int s1i = __ldg(&edges[e + 1]);
        int s2i = __ldg(&edges[e + 2]);
        int s3i = __ldg(&edges[e + 3]);
        float c0 = __ldg(&dinv[s0i]) * di;
        float c1 = __ldg(&dinv[s1i]) * di;
        float c2 = __ldg(&dinv[s2i]) * di;
        float c3 = __ldg(&dinv[s3i]) * di;
        float4 v0 = *reinterpret_cast<const float4*>(&hw[(size_t)s0i * DTOT + f]);
        float4 v1 = *reinterpret_cast<const float4*>(&hw[(size_t)s1i * DTOT + f]);
        float4 v2 = *reinterpret_cast<const float4*>(&hw[(size_t)s2i * DTOT + f]);
        float4 v3 = *reinterpret_cast<const float4*>(&hw[(size_t)s3i * DTOT + f]);
        acc.x = fmaf(v0.x, c0, acc.x); acc.y = fmaf(v0.y, c0, acc.y);
        acc.z = fmaf(v0.z, c0, acc.z); acc.w = fmaf(v0.w, c0, acc.w);
        acc.x = fmaf(v1.x, c1, acc.x); acc.y = fmaf(v1.y, c1, acc.y);
        acc.z = fmaf(v1.z, c1, acc.z); acc.w = fmaf(v1.w, c1, acc.w);
        acc.x = fmaf(v2.x, c2, acc.x); acc.y = fmaf(v2.y, c2, acc.y);
        acc.z = fmaf(v2.z, c2, acc.z); acc.w = fmaf(v2.w, c2, acc.w);
        acc.x = fmaf(v3.x, c3, acc.x); acc.y = fmaf(v3.y, c3, acc.y);
        acc.z = fmaf(v3.z, c3, acc.z); acc.w = fmaf(v3.w, c3, acc.w);
    }
    for (; e < end; e++) {
        int s0i = __ldg(&edges[e]);
        float c0 = __ldg(&dinv[s0i]) * di;
        float4 v0 = *reinterpret_cast<const float4*>(&hw[(size_t)s0i * DTOT + f]);
        acc.x = fmaf(v0.x, c0, acc.x); acc.y = fmaf(v0.y, c0, acc.y);
        acc.z = fmaf(v0.z, c0, acc.z); acc.w = fmaf(v0.w, c0, acc.w);
    }

    if (RELU) {
        acc.x = fmaxf(acc.x, 0.f); acc.y = fmaxf(acc.y, 0.f);
        acc.z = fmaxf(acc.z, 0.f); acc.w = fmaxf(acc.w, 0.f);
    }
    if (SPLIT) {
        __nv_bfloat162 h0, l0, h1, l1;
        split2(acc.x, acc.y, h0, l0);
        split2(acc.z, acc.w, h1, l1);
        *reinterpret_cast<__nv_bfloat162*>(&outHi[(size_t)n * DTOT + f])     = h0;
        *reinterpret_cast<__nv_bfloat162*>(&outHi[(size_t)n * DTOT + f + 2]) = h1;
        *reinterpret_cast<__nv_bfloat162*>(&outLo[(size_t)n * DTOT + f])     = l0;
        *reinterpret_cast<__nv_bfloat162*>(&outLo[(size_t)n * DTOT + f + 2]) = l1;
    } else if (FINAL) {
        st_cs_f4(&out[(size_t)n * DTOT + f], acc);
    } else {
        *reinterpret_cast<float4*>(&out[(size_t)n * DTOT + f]) = acc;
    }
}

// ---------------- launch ----------------

extern "C" void kernel_launch(void* const* d_in, const int* in_sizes, int n_in,
                              void* d_out, int out_size)
{
    const float* x  = (const float*)d_in[0];
    const int*   ei = (const int*)  d_in[1];
    const float* W0 = (const float*)d_in[4];
    const float* b0 = (const float*)d_in[5];
    const float* W1 = (const float*)d_in[6];
    const float* b1 = (const float*)d_in[7];
    const float* W2 = (const float*)d_in[8];
    const float* b2 = (const float*)d_in[9];

    int N = in_sizes[0] / 128;
    int E = in_sizes[1] / 2;
    const int* rowp = ei;
    const int* colp = ei + E;

    float *bufF, *dinv;
    __nv_bfloat16 *bAHi, *bALo, *bBHi, *bBLo, *wtHi, *wtLo;
    int *cnt, *rowptr, *cursor, *blockSums;
    int *edges;
    cudaGetSymbolAddress((void**)&bufF,      g_bufF);
    cudaGetSymbolAddress((void**)&bAHi,      g_bAHi);
    cudaGetSymbolAddress((void**)&bALo,      g_bALo);
    cudaGetSymbolAddress((void**)&bBHi,      g_bBHi);
    cudaGetSymbolAddress((void**)&bBLo,      g_bBLo);
    cudaGetSymbolAddress((void**)&wtHi,      g_wtHi);
    cudaGetSymbolAddress((void**)&wtLo,      g_wtLo);
    cudaGetSymbolAddress((void**)&dinv,      g_dinv);
    cudaGetSymbolAddress((void**)&cnt,       g_cnt);
    cudaGetSymbolAddress((void**)&rowptr,    g_rowptr);
    cudaGetSymbolAddress((void**)&cursor,    g_cursor);
    cudaGetSymbolAddress((void**)&blockSums, g_blockSums);
    cudaGetSymbolAddress((void**)&edges,     g_edges);

    float* outp = (float*)d_out;

    static cudaStream_t s2 = nullptr;
    static cudaEvent_t evFork = nullptr, evJoin = nullptr;
    static bool initDone = false;
    if (!initDone) {
        cudaFuncSetAttribute(k_gemm_mma<0>, cudaFuncAttributeMaxDynamicSharedMemorySize,
                             SMEM_TOTAL_G);
        cudaFuncSetAttribute(k_gemm_mma<1>, cudaFuncAttributeMaxDynamicSharedMemorySize,
                             SMEM_TOTAL_G);
        cudaStreamCreateWithFlags(&s2, cudaStreamNonBlocking);
        cudaEventCreateWithFlags(&evFork, cudaEventDisableTiming);
        cudaEventCreateWithFlags(&evJoin, cudaEventDisableTiming);
        initDone = true;
    }

    int nb = (N + SCAN_ITEMS - 1) / SCAN_ITEMS;

    // ---- fork: fused weight split on side stream
    cudaEventRecord(evFork, 0);
    cudaStreamWaitEvent(s2, evFork, 0);
    k_split_wt_all<<<(131072 + 255) / 256, 256, 0, s2>>>(W0, W1, W2, wtHi, wtLo);
    cudaEventRecord(evJoin, s2);

    // ---- main stream: CSR build + norm (memset node replaces zero kernel)
    cudaMemsetAsync(cnt, 0, (size_t)N * sizeof(int), 0);
    k_hist    <<<(E / 4 + 255) / 256, 256>>>(colp, cnt, E);
    k_scan1d  <<<nb, 256>>>(cnt, rowptr, blockSums, dinv, N);
    k_scan3b  <<<(N + 255) / 256, 256>>>(rowptr, cursor, blockSums, nb, N, E);
    k_scatter <<<(E / 4 + 255) / 256, 256>>>(rowp, colp, cursor, edges, E);

    int mt = (N + 127) / 128;
    int gatherBlocks = (N * 32 + 255) / 256;

    // L0 (aggregate-first): xa = Â x (D=128), split -> bA
    k_gather<128, false, true, false><<<gatherBlocks, 256>>>(x, nullptr, dinv, rowptr, edges,
                                                             nullptr, bAHi, bALo, N, 0);

    cudaStreamWaitEvent(0, evJoin, 0);

    // GEMM0: h1 = relu(xa@W0 + b0), split epilogue -> bB
    k_gemm_mma<1><<<dim3(2, mt), 256, SMEM_TOTAL_G>>>(bAHi, bALo,
                                                      wtHi + 0 * 65536, wtLo + 0 * 65536,
                                                      nullptr, b0, bBHi, bBLo, N, 128, 256);
    // L1: bufF = h1@W1; h2 = relu(Â bufF + b1), split -> bA
    // single launch, gridDim.y = 2 feature passes (x-major order keeps phasing)
    k_gemm_mma<0><<<dim3(2, mt), 256, SMEM_TOTAL_G>>>(bBHi, bBLo,
                                                      wtHi + 1 * 65536, wtLo + 1 * 65536,
                                                      bufF, nullptr, nullptr, nullptr, N, 256, 256);
    k_gather<256, true, true, false><<<dim3(gatherBlocks, 2), 256>>>(bufF, b1, dinv, rowptr, edges,
                                                                     nullptr, bAHi, bALo, N, 0);
    // L2: bufF = h2@W2 (D=128); out = Â bufF + b2
    k_gemm_mma<0><<<dim3(1, mt), 256, SMEM_TOTAL_G>>>(bAHi, bALo,
                                                      wtHi + 2 * 65536, wtLo + 2 * 65536,
                                                      bufF, nullptr, nullptr, nullptr, N, 256, 128);
    k_gather<128, false, false, true><<<gatherBlocks, 256>>>(bufF, b2, dinv, rowptr, edges,
                                                             outp, nullptr, nullptr, N, 0);
}